// round 16
// baseline (speedup 1.0000x reference)
#include <cuda_runtime.h>
#include <cuda_fp16.h>

#define N_NODES 100000
#define N_EDGES 1600000
#define HDIM    64
#define N_EMB   174   // sum of ATOM_DIMS
#define NFEAT   9
#define QK_SCALE 0.35355339059327373f  // 1/sqrt(8)

#define MAXDEG  96    // P(Binomial(1.6M,1e-5) > 96) ~ 1e-40 — never trips
#define ZERO_NB 391   // ceil(100000/256)
#define WO_NB   16    // 16*256 = 4096 = Wo elements
#define QKV_NB  6250  // 6250*256/16 = 100000 nodes exactly
#define EDGE_NB 6250
#define OUT_NB  782   // ceil(100000/128)

#define FUSED_STRIDE 25000            // warps; 4 nodes per warp
#define FUSED_NB     3125             // 25000*32/256

__constant__ int c_offs[NFEAT] = {0, 119, 124, 136, 148, 158, 164, 170, 172};

// All node vectors live in head-major "p-order": p = (d&7)*8 + (d>>3)
// (self-inverse permutation). Applied once at emb-table build.

// ---------------- scratch (device globals; no allocations allowed) ----------
__device__ float    g_embQ[N_EMB * HDIM];
__device__ float    g_embK[N_EMB * HDIM];
__device__ float    g_embV[N_EMB * HDIM];
__device__ float    g_Q[N_NODES * HDIM];
__device__ float    g_K[N_NODES * HDIM];
__device__ __half   g_Vh[N_NODES * HDIM];
__device__ __half   g_AVh[N_NODES * HDIM];
__device__ __half   g_Woh[HDIM * HDIM];      // fp16, rows already permuted
__device__ int      g_cnt [N_NODES];
__device__ int      g_scol[(size_t)N_NODES * MAXDEG];  // fixed-stride adjacency
                                                       // (zero-init; unwritten slots = node 0, safe)

// ---------------- K_prep: zero counters + permuted tables + fp16 Wo ---------
__global__ void k_prep(const float* __restrict__ emb,
                       const float* __restrict__ Wq, const float* __restrict__ bq,
                       const float* __restrict__ Wk, const float* __restrict__ bk,
                       const float* __restrict__ Wv, const float* __restrict__ bv,
                       const float* __restrict__ Wo) {
    int b = blockIdx.x, t = threadIdx.x;
    if (b < ZERO_NB) {                       // zero the degree counters
        int i = b * 256 + t;
        if (i < N_NODES) g_cnt[i] = 0;
        return;
    }
    if (b < ZERO_NB + WO_NB) {               // pre-permute + quantize Wo
        int idx = (b - ZERO_NB) * 256 + t;   // d*64 + c
        int d = idx >> 6, c = idx & 63;
        int p = ((d & 7) << 3) + (d >> 3);
        g_Woh[p * HDIM + c] = __float2half(Wo[idx]);
        return;
    }
    int r = b - ZERO_NB - WO_NB;             // emb row 0..173
    __shared__ float a[HDIM];
    if (t < HDIM) a[t] = emb[r * HDIM + t];
    __syncthreads();
    if (t >= 192) return;
    int mat = t >> 6, c = t & 63;
    const float* W = (mat == 0) ? Wq : (mat == 1) ? Wk : Wv;
    float acc = 0.f;
    #pragma unroll
    for (int j = 0; j < HDIM; j++) acc += a[j] * W[j * HDIM + c];
    // fold bias into the feature-0 rows (every node uses exactly one of them)
    if (r < 119) acc += ((mat == 0) ? bq : (mat == 1) ? bk : bv)[c];
    int p = ((c & 7) << 3) + (c >> 3);       // head-major position
    if (mat == 0)      g_embQ[r * HDIM + p] = acc * QK_SCALE;
    else if (mat == 1) g_embK[r * HDIM + p] = acc;
    else               g_embV[r * HDIM + p] = acc;
}

// ---------------- K_gather_scatter: node QKV gather  ||  edge adjacency -----
__global__ void k_gather_scatter(const int* __restrict__ X,
                                 const int* __restrict__ row,
                                 const int* __restrict__ col) {
    int b = blockIdx.x, t = threadIdx.x;
    if (b >= QKV_NB) {                       // adjacency half of the grid
        int e = (b - QKV_NB) * 256 + t;
        if (e < N_EDGES) {
            int r = __ldg(&row[e]);
            int pos = atomicAdd(&g_cnt[r], 1);
            if (pos < MAXDEG) g_scol[(size_t)r * MAXDEG + pos] = __ldg(&col[e]);
        }
        return;
    }
    int tid = b * 256 + t;
    int n = tid >> 4, t16 = tid & 15;        // 16 threads/node, float4 each

    const float4* eq = (const float4*)g_embQ;
    const float4* ek = (const float4*)g_embK;
    const float4* ev = (const float4*)g_embV;

    float4 aq = make_float4(0.f, 0.f, 0.f, 0.f);
    float4 ak = aq, av = aq;
    #pragma unroll
    for (int f = 0; f < NFEAT; f++) {
        int idx = X[n * NFEAT + f] + c_offs[f];
        int base = idx * 16 + t16;
        float4 q = eq[base]; aq.x += q.x; aq.y += q.y; aq.z += q.z; aq.w += q.w;
        float4 k = ek[base]; ak.x += k.x; ak.y += k.y; ak.z += k.z; ak.w += k.w;
        float4 v = ev[base]; av.x += v.x; av.y += v.y; av.z += v.z; av.w += v.w;
    }
    ((float4*)g_Q)[n * 16 + t16] = aq;
    ((float4*)g_K)[n * 16 + t16] = ak;
    __half2 v01 = __floats2half2_rn(av.x, av.y);
    __half2 v23 = __floats2half2_rn(av.z, av.w);
    uint2 o;
    o.x = *(unsigned*)&v01; o.y = *(unsigned*)&v23;
    *(uint2*)(g_Vh + n * HDIM + 4 * t16) = o;
}

// ---------------- K_fused: SDDMM + softmax + SpMM (16 lanes/edge) -----------
// 4 nodes per warp (stride FUSED_STRIDE) with 1-node-deep prefetch: while the
// edge loop for node i runs, node i+1's cnt / scol-row / Q loads are already
// in flight — prologue latency fully overlapped, higher sustained MLP.
// Inner loop identical to R15 (unroll 4; do NOT raise — R14 regression).
__global__ __launch_bounds__(256) void k_fused() {
    int w = (blockIdx.x * blockDim.x + threadIdx.x) >> 5;
    int lane = threadIdx.x & 31;
    int slot = lane >> 4, t = lane & 15;

    int n = w;                                // node 0 of this warp
    int len   = min(__ldg(&g_cnt[n]), MAXDEG);
    int c_reg = __ldg(&g_scol[(size_t)n * MAXDEG + lane]);
    float4 q  = ((const float4*)(g_Q + n * HDIM))[t];

    #pragma unroll
    for (int it = 0; it < 4; it++) {
        // prefetch next node's state (independent loads; consumed after loop)
        int n2 = n + FUSED_STRIDE;
        int len2 = 0, c2 = 0;
        float4 q2 = make_float4(0.f, 0.f, 0.f, 0.f);
        if (it < 3) {
            len2 = min(__ldg(&g_cnt[n2]), MAXDEG);
            c2   = __ldg(&g_scol[(size_t)n2 * MAXDEG + lane]);
            q2   = ((const float4*)(g_Q + n2 * HDIM))[t];
        }

        size_t base = (size_t)n * MAXDEG;
        float sum = 0.f;
        float4 acc = make_float4(0.f, 0.f, 0.f, 0.f);
        #pragma unroll 4
        for (int i = 0; i < len; i += 2) {
            int idx = i + slot;
            bool valid = idx < len;
            int c;
            if (i + 1 < 32) c = __shfl_sync(0xffffffffu, c_reg, idx);
            else            c = __ldg(&g_scol[base + (valid ? idx : i)]);
            float4 k = __ldg(((const float4*)(g_K + c * HDIM)) + t);
            uint2 vraw = __ldg((const uint2*)(g_Vh + c * HDIM + 4 * t));
            float2 v01 = __half22float2(*(__half2*)&vraw.x);
            float2 v23 = __half22float2(*(__half2*)&vraw.y);
            float s = q.x * k.x + q.y * k.y + q.z * k.z + q.w * k.w;
            s += __shfl_xor_sync(0xffffffffu, s, 1);   // pair -> full head dot
            float p = valid ? __expf(s) : 0.f;
            sum += p;
            acc.x += p * v01.x; acc.y += p * v01.y;
            acc.z += p * v23.x; acc.w += p * v23.y;
        }
        sum   += __shfl_xor_sync(0xffffffffu, sum,   16);
        acc.x += __shfl_xor_sync(0xffffffffu, acc.x, 16);
        acc.y += __shfl_xor_sync(0xffffffffu, acc.y, 16);
        acc.z += __shfl_xor_sync(0xffffffffu, acc.z, 16);
        acc.w += __shfl_xor_sync(0xffffffffu, acc.w, 16);
        float inv = (len > 0) ? (1.0f / sum) : 0.f;
        if (lane < 16) {
            __half2 o01 = __floats2half2_rn(acc.x * inv, acc.y * inv);
            __half2 o23 = __floats2half2_rn(acc.z * inv, acc.w * inv);
            uint2 o;
            o.x = *(unsigned*)&o01; o.y = *(unsigned*)&o23;
            *(uint2*)(g_AVh + n * HDIM + 4 * t) = o;
        }

        n = n2; len = len2; c_reg = c2; q = q2;   // rotate in prefetched state
    }
}

// ---------------- K_out: tensor-core GEMM  out = AV @ Wo + bo ---------------
// Block = 256 threads (8 warps), 128 nodes/block. Wo staged from the
// pre-permuted fp16 copy (8 KB, no index math); AV tile staged as half2
// (R13 layout — measured 12.8us; uint4 staging regressed, do not re-apply).
__global__ __launch_bounds__(256) void k_out(const float* __restrict__ bo,
                                             float* __restrict__ out) {
    __shared__ __half Ws[HDIM][72];          // [k_p][c]
    __shared__ __half As[128][72];           // [node][k_p]
    __shared__ float  bos[HDIM];

    int t = threadIdx.x;
    size_t nb = (size_t)blockIdx.x * 128;

    // stage pre-permuted fp16 Wo (coalesced half2)
    #pragma unroll
    for (int j = 0; j < 8; j++) {
        int idx = t + 256 * j;               // 2048 half2
        int d = idx >> 5, k2 = idx & 31;
        *(__half2*)&Ws[d][2 * k2] = ((const __half2*)g_Woh)[idx];
    }
    if (t < HDIM) bos[t] = bo[t];

    // stage AV tile (coalesced half2)
    #pragma unroll
    for (int j = 0; j < 16; j++) {
        int idx = t + 256 * j;               // 4096 half2
        int r = idx >> 5, k2 = idx & 31;
        __half2 h = (nb + r < N_NODES)
                  ? ((const __half2*)g_AVh)[(nb + r) * 32 + k2]
                  : __float2half2_rn(0.f);
        *(__half2*)&As[r][2 * k2] = h;
    }
    __syncthreads();

    int w = t >> 5, l = t & 31;

    // A fragments: 4 k-steps of m16k16
    unsigned a[4][4];
    #pragma unroll
    for (int kk = 0; kk < 4; kk++) {
        unsigned addr = (unsigned)__cvta_generic_to_shared(
            &As[w * 16 + (l & 15)][kk * 16 + (l >> 4) * 8]);
        asm volatile("ldmatrix.sync.aligned.m8n8.x4.shared.b16 {%0,%1,%2,%3}, [%4];"
                     : "=r"(a[kk][0]), "=r"(a[kk][1]), "=r"(a[kk][2]), "=r"(a[kk][3])
                     : "r"(addr));
    }

    int g0 = l >> 2;                         // C-fragment row group
    int c0 = (l & 3) * 2;
    #pragma unroll
    for (int nt = 0; nt < 8; nt++) {
        float d0 = 0.f, d1 = 0.f, d2 = 0.f, d3 = 0.f;
        #pragma unroll
        for (int kk = 0; kk < 4; kk++) {
            unsigned b0, b1;
            unsigned baddr = (unsigned)__cvta_generic_to_shared(
                &Ws[kk * 16 + (l & 15)][nt * 8]);
            asm volatile("ldmatrix.sync.aligned.m8n8.x2.trans.shared.b16 {%0,%1}, [%2];"
                         : "=r"(b0), "=r"(b1) : "r"(baddr));
            asm volatile(
                "mma.sync.aligned.m16n8k16.row.col.f32.f16.f16.f32 "
                "{%0,%1,%2,%3},{%4,%5,%6,%7},{%8,%9},{%0,%1,%2,%3};"
                : "+f"(d0), "+f"(d1), "+f"(d2), "+f"(d3)
                : "r"(a[kk][0]), "r"(a[kk][1]), "r"(a[kk][2]), "r"(a[kk][3]),
                  "r"(b0), "r"(b1));
        }
        int cc = nt * 8 + c0;
        float bx = bos[cc], by = bos[cc + 1];
        size_t n0 = nb + w * 16 + g0;
        if (n0 < N_NODES)
            *(float2*)&out[n0 * HDIM + cc] = make_float2(d0 + bx, d1 + by);
        if (n0 + 8 < N_NODES)
            *(float2*)&out[(n0 + 8) * HDIM + cc] = make_float2(d2 + bx, d3 + by);
    }
}

// ---------------- launch -----------------------------------------------------
extern "C" void kernel_launch(void* const* d_in, const int* in_sizes, int n_in,
                              void* d_out, int out_size) {
    const int*   X        = (const int*)  d_in[0];
    const int*   row      = (const int*)  d_in[1];
    const int*   col      = (const int*)  d_in[2];
    const float* atom_emb = (const float*)d_in[3];
    const float* Wq       = (const float*)d_in[4];
    const float* bq       = (const float*)d_in[5];
    const float* Wk       = (const float*)d_in[6];
    const float* bk       = (const float*)d_in[7];
    const float* Wv       = (const float*)d_in[8];
    const float* bv       = (const float*)d_in[9];
    const float* Wo       = (const float*)d_in[10];
    const float* bo       = (const float*)d_in[11];
    float* out = (float*)d_out;

    (void)in_sizes; (void)n_in; (void)out_size;

    k_prep<<<ZERO_NB + WO_NB + N_EMB, 256>>>(atom_emb, Wq, bq, Wk, bk, Wv, bv, Wo);
    k_gather_scatter<<<QKV_NB + EDGE_NB, 256>>>(X, row, col);
    k_fused<<<FUSED_NB, 256>>>();
    k_out<<<OUT_NB, 256>>>(bo, out);
}

// round 17
// speedup vs baseline: 1.1507x; 1.1507x over previous
#include <cuda_runtime.h>
#include <cuda_fp16.h>

#define N_NODES 100000
#define N_EDGES 1600000
#define HDIM    64
#define N_EMB   174   // sum of ATOM_DIMS
#define NFEAT   9
#define QK_SCALE 0.35355339059327373f  // 1/sqrt(8)

#define MAXDEG  96    // P(Binomial(1.6M,1e-5) > 96) ~ 1e-40 — never trips
#define ZERO_NB 391   // ceil(100000/256)
#define WO_NB   16    // 16*256 = 4096 = Wo elements
#define QKV_NB  6250  // 6250*256/16 = 100000 nodes exactly
#define EDGE_NB 3125  // 3125*256*2 = 1.6M edges, 2 per thread
#define OUT_NB  782   // ceil(100000/128)

__constant__ int c_offs[NFEAT] = {0, 119, 124, 136, 148, 158, 164, 170, 172};

// All node vectors live in head-major "p-order": p = (d&7)*8 + (d>>3)
// (self-inverse permutation). Applied once at emb-table build.

// ---------------- scratch (device globals; no allocations allowed) ----------
__device__ float    g_embQ[N_EMB * HDIM];
__device__ float    g_embK[N_EMB * HDIM];
__device__ float    g_embV[N_EMB * HDIM];
__device__ float    g_Q[N_NODES * HDIM];
__device__ float    g_K[N_NODES * HDIM];
__device__ __half   g_Vh[N_NODES * HDIM];
__device__ __half   g_AVh[N_NODES * HDIM];
__device__ __half   g_Woh[HDIM * HDIM];      // fp16, rows already permuted
__device__ int      g_cnt [N_NODES];
__device__ int      g_scol[(size_t)N_NODES * MAXDEG];  // fixed-stride adjacency
                                                       // (zero-init; unwritten slots = node 0, safe)

// ---------------- K_prep: zero counters + permuted tables + fp16 Wo ---------
__global__ void k_prep(const float* __restrict__ emb,
                       const float* __restrict__ Wq, const float* __restrict__ bq,
                       const float* __restrict__ Wk, const float* __restrict__ bk,
                       const float* __restrict__ Wv, const float* __restrict__ bv,
                       const float* __restrict__ Wo) {
    int b = blockIdx.x, t = threadIdx.x;
    if (b < ZERO_NB) {                       // zero the degree counters
        int i = b * 256 + t;
        if (i < N_NODES) g_cnt[i] = 0;
        return;
    }
    if (b < ZERO_NB + WO_NB) {               // pre-permute + quantize Wo
        int idx = (b - ZERO_NB) * 256 + t;   // d*64 + c
        int d = idx >> 6, c = idx & 63;
        int p = ((d & 7) << 3) + (d >> 3);
        g_Woh[p * HDIM + c] = __float2half(Wo[idx]);
        return;
    }
    int r = b - ZERO_NB - WO_NB;             // emb row 0..173
    __shared__ float a[HDIM];
    if (t < HDIM) a[t] = emb[r * HDIM + t];
    __syncthreads();
    if (t >= 192) return;
    int mat = t >> 6, c = t & 63;
    const float* W = (mat == 0) ? Wq : (mat == 1) ? Wk : Wv;
    float acc = 0.f;
    #pragma unroll
    for (int j = 0; j < HDIM; j++) acc += a[j] * W[j * HDIM + c];
    // fold bias into the feature-0 rows (every node uses exactly one of them)
    if (r < 119) acc += ((mat == 0) ? bq : (mat == 1) ? bk : bv)[c];
    int p = ((c & 7) << 3) + (c >> 3);       // head-major position
    if (mat == 0)      g_embQ[r * HDIM + p] = acc * QK_SCALE;
    else if (mat == 1) g_embK[r * HDIM + p] = acc;
    else               g_embV[r * HDIM + p] = acc;
}

// ---------------- K_gather_scatter: node QKV gather  ||  edge adjacency -----
// Scatter half: 2 edges per thread (two independent atomic/store chains).
__global__ void k_gather_scatter(const int* __restrict__ X,
                                 const int* __restrict__ row,
                                 const int* __restrict__ col) {
    int b = blockIdx.x, t = threadIdx.x;
    if (b >= QKV_NB) {                       // adjacency half of the grid
        int e0 = (b - QKV_NB) * 512 + t;     // edges e0 and e0+256
        int r0 = __ldg(&row[e0]);
        int r1 = __ldg(&row[e0 + 256]);
        int c0 = __ldg(&col[e0]);
        int c1 = __ldg(&col[e0 + 256]);
        int p0 = atomicAdd(&g_cnt[r0], 1);
        int p1 = atomicAdd(&g_cnt[r1], 1);
        if (p0 < MAXDEG) g_scol[(size_t)r0 * MAXDEG + p0] = c0;
        if (p1 < MAXDEG) g_scol[(size_t)r1 * MAXDEG + p1] = c1;
        return;
    }
    int tid = b * 256 + t;
    int n = tid >> 4, t16 = tid & 15;        // 16 threads/node, float4 each

    const float4* eq = (const float4*)g_embQ;
    const float4* ek = (const float4*)g_embK;
    const float4* ev = (const float4*)g_embV;

    float4 aq = make_float4(0.f, 0.f, 0.f, 0.f);
    float4 ak = aq, av = aq;
    #pragma unroll
    for (int f = 0; f < NFEAT; f++) {
        int idx = X[n * NFEAT + f] + c_offs[f];
        int base = idx * 16 + t16;
        float4 q = eq[base]; aq.x += q.x; aq.y += q.y; aq.z += q.z; aq.w += q.w;
        float4 k = ek[base]; ak.x += k.x; ak.y += k.y; ak.z += k.z; ak.w += k.w;
        float4 v = ev[base]; av.x += v.x; av.y += v.y; av.z += v.z; av.w += v.w;
    }
    ((float4*)g_Q)[n * 16 + t16] = aq;
    ((float4*)g_K)[n * 16 + t16] = ak;
    __half2 v01 = __floats2half2_rn(av.x, av.y);
    __half2 v23 = __floats2half2_rn(av.z, av.w);
    uint2 o;
    o.x = *(unsigned*)&v01; o.y = *(unsigned*)&v23;
    *(uint2*)(g_Vh + n * HDIM + 4 * t16) = o;
}

// ---------------- K_fused: SDDMM + softmax + SpMM (16 lanes/edge) -----------
// R15 form EXACTLY — measured champion. L2-throughput bound (~384 B/edge at
// the LTS cap); unroll-8 (R14) and node-prefetch (R16) both regressed it.
// Do not touch the loop structure.
__global__ __launch_bounds__(256) void k_fused() {
    int g = blockIdx.x * blockDim.x + threadIdx.x;
    int n = g >> 5;
    if (n >= N_NODES) return;
    int lane = threadIdx.x & 31;
    int slot = lane >> 4, t = lane & 15;
    size_t base = (size_t)n * MAXDEG;
    int len = min(g_cnt[n], MAXDEG);

    int c_reg = __ldg(&g_scol[base + lane]); // edges 0..31 (zero-init tail safe)
    float4 q = ((const float4*)(g_Q + n * HDIM))[t];

    float sum = 0.f;
    float4 acc = make_float4(0.f, 0.f, 0.f, 0.f);
    #pragma unroll 4
    for (int i = 0; i < len; i += 2) {
        int idx = i + slot;
        bool valid = idx < len;
        int c;
        if (i + 1 < 32) c = __shfl_sync(0xffffffffu, c_reg, idx);
        else            c = __ldg(&g_scol[base + (valid ? idx : i)]);
        float4 k = __ldg(((const float4*)(g_K + c * HDIM)) + t);
        uint2 vraw = __ldg((const uint2*)(g_Vh + c * HDIM + 4 * t));
        float2 v01 = __half22float2(*(__half2*)&vraw.x);
        float2 v23 = __half22float2(*(__half2*)&vraw.y);
        float s = q.x * k.x + q.y * k.y + q.z * k.z + q.w * k.w;
        s += __shfl_xor_sync(0xffffffffu, s, 1);   // pair -> full head dot
        float p = valid ? __expf(s) : 0.f;
        sum += p;
        acc.x += p * v01.x; acc.y += p * v01.y;
        acc.z += p * v23.x; acc.w += p * v23.y;
    }
    sum   += __shfl_xor_sync(0xffffffffu, sum,   16);
    acc.x += __shfl_xor_sync(0xffffffffu, acc.x, 16);
    acc.y += __shfl_xor_sync(0xffffffffu, acc.y, 16);
    acc.z += __shfl_xor_sync(0xffffffffu, acc.z, 16);
    acc.w += __shfl_xor_sync(0xffffffffu, acc.w, 16);
    float inv = (len > 0) ? (1.0f / sum) : 0.f;
    if (lane < 16) {
        __half2 o01 = __floats2half2_rn(acc.x * inv, acc.y * inv);
        __half2 o23 = __floats2half2_rn(acc.z * inv, acc.w * inv);
        uint2 o;
        o.x = *(unsigned*)&o01; o.y = *(unsigned*)&o23;
        *(uint2*)(g_AVh + n * HDIM + 4 * t) = o;
    }
}

// ---------------- K_out: tensor-core GEMM  out = AV @ Wo + bo ---------------
// Block = 256 threads (8 warps), 128 nodes/block. Wo staged from the
// pre-permuted fp16 copy (8 KB, no index math); AV tile staged as half2
// (R13 layout — measured 12.8us; uint4 staging regressed, do not re-apply).
__global__ __launch_bounds__(256) void k_out(const float* __restrict__ bo,
                                             float* __restrict__ out) {
    __shared__ __half Ws[HDIM][72];          // [k_p][c]
    __shared__ __half As[128][72];           // [node][k_p]
    __shared__ float  bos[HDIM];

    int t = threadIdx.x;
    size_t nb = (size_t)blockIdx.x * 128;

    // stage pre-permuted fp16 Wo (coalesced half2)
    #pragma unroll
    for (int j = 0; j < 8; j++) {
        int idx = t + 256 * j;               // 2048 half2
        int d = idx >> 5, k2 = idx & 31;
        *(__half2*)&Ws[d][2 * k2] = ((const __half2*)g_Woh)[idx];
    }
    if (t < HDIM) bos[t] = bo[t];

    // stage AV tile (coalesced half2)
    #pragma unroll
    for (int j = 0; j < 16; j++) {
        int idx = t + 256 * j;               // 4096 half2
        int r = idx >> 5, k2 = idx & 31;
        __half2 h = (nb + r < N_NODES)
                  ? ((const __half2*)g_AVh)[(nb + r) * 32 + k2]
                  : __float2half2_rn(0.f);
        *(__half2*)&As[r][2 * k2] = h;
    }
    __syncthreads();

    int w = t >> 5, l = t & 31;

    // A fragments: 4 k-steps of m16k16
    unsigned a[4][4];
    #pragma unroll
    for (int kk = 0; kk < 4; kk++) {
        unsigned addr = (unsigned)__cvta_generic_to_shared(
            &As[w * 16 + (l & 15)][kk * 16 + (l >> 4) * 8]);
        asm volatile("ldmatrix.sync.aligned.m8n8.x4.shared.b16 {%0,%1,%2,%3}, [%4];"
                     : "=r"(a[kk][0]), "=r"(a[kk][1]), "=r"(a[kk][2]), "=r"(a[kk][3])
                     : "r"(addr));
    }

    int g0 = l >> 2;                         // C-fragment row group
    int c0 = (l & 3) * 2;
    #pragma unroll
    for (int nt = 0; nt < 8; nt++) {
        float d0 = 0.f, d1 = 0.f, d2 = 0.f, d3 = 0.f;
        #pragma unroll
        for (int kk = 0; kk < 4; kk++) {
            unsigned b0, b1;
            unsigned baddr = (unsigned)__cvta_generic_to_shared(
                &Ws[kk * 16 + (l & 15)][nt * 8]);
            asm volatile("ldmatrix.sync.aligned.m8n8.x2.trans.shared.b16 {%0,%1}, [%2];"
                         : "=r"(b0), "=r"(b1) : "r"(baddr));
            asm volatile(
                "mma.sync.aligned.m16n8k16.row.col.f32.f16.f16.f32 "
                "{%0,%1,%2,%3},{%4,%5,%6,%7},{%8,%9},{%0,%1,%2,%3};"
                : "+f"(d0), "+f"(d1), "+f"(d2), "+f"(d3)
                : "r"(a[kk][0]), "r"(a[kk][1]), "r"(a[kk][2]), "r"(a[kk][3]),
                  "r"(b0), "r"(b1));
        }
        int cc = nt * 8 + c0;
        float bx = bos[cc], by = bos[cc + 1];
        size_t n0 = nb + w * 16 + g0;
        if (n0 < N_NODES)
            *(float2*)&out[n0 * HDIM + cc] = make_float2(d0 + bx, d1 + by);
        if (n0 + 8 < N_NODES)
            *(float2*)&out[(n0 + 8) * HDIM + cc] = make_float2(d2 + bx, d3 + by);
    }
}

// ---------------- launch -----------------------------------------------------
extern "C" void kernel_launch(void* const* d_in, const int* in_sizes, int n_in,
                              void* d_out, int out_size) {
    const int*   X        = (const int*)  d_in[0];
    const int*   row      = (const int*)  d_in[1];
    const int*   col      = (const int*)  d_in[2];
    const float* atom_emb = (const float*)d_in[3];
    const float* Wq       = (const float*)d_in[4];
    const float* bq       = (const float*)d_in[5];
    const float* Wk       = (const float*)d_in[6];
    const float* bk       = (const float*)d_in[7];
    const float* Wv       = (const float*)d_in[8];
    const float* bv       = (const float*)d_in[9];
    const float* Wo       = (const float*)d_in[10];
    const float* bo       = (const float*)d_in[11];
    float* out = (float*)d_out;

    (void)in_sizes; (void)n_in; (void)out_size;

    k_prep<<<ZERO_NB + WO_NB + N_EMB, 256>>>(atom_emb, Wq, bq, Wk, bk, Wv, bv, Wo);
    k_gather_scatter<<<QKV_NB + EDGE_NB, 256>>>(X, row, col);
    k_fused<<<(N_NODES * 32 + 255) / 256, 256>>>();
    k_out<<<OUT_NB, 256>>>(bo, out);
}